// round 6
// baseline (speedup 1.0000x reference)
#include <cuda_runtime.h>
#include <math.h>

#define NN 100000
#define NE 1600000
#define NG 64
#define FD 50
#define ES 656      // ext row stride (pad 650 -> 656, 16B aligned)
#define KPAD 656
#define CST 64      // combined-weight column stride (pad 50 -> 64)
#define NL 3

// ---------------- static scratch (no allocation allowed) ----------------
__device__ int    g_deg[NN];
__device__ int    g_rowptr[NN + 1];
__device__ int    g_cursor[NN];
__device__ int    g_col[NE];
__device__ float  g_dinv[NN];
__device__ float  g_amp[NN];
__device__ float  g_att[NN];
__device__ double g_avg;
__device__ float  g_h[NN * FD];
__device__ float  g_h2[NN * FD];
__device__ float  g_h0s[NN * FD];
__device__ float  g_base[NN * FD];
__device__ float  g_y[NN * FD];
__device__ float  g_ext[(size_t)NN * ES];      // ~262 MB
__device__ float  g_C[NL * KPAD * CST];
__device__ float  g_bcm[NL * CST];
__device__ double g_bns[2 * CST];
__device__ float  g_scale[CST];
__device__ float  g_shift[CST];
__device__ float  g_gr[NG * FD];

// ---------------- setup kernels ----------------
__global__ void __launch_bounds__(256) k_zero0() {
    int i = blockIdx.x * 256 + threadIdx.x;
    if (i < NN) g_deg[i] = 0;
    if (i == 0) g_avg = 0.0;
}

__global__ void __launch_bounds__(256) k_hist(const int* __restrict__ dst) {
    int e = blockIdx.x * 256 + threadIdx.x;
    if (e < NE) atomicAdd(&g_deg[dst[e]], 1);
}

#define SCAN_T 1024
#define SCAN_CHUNK 98   // 1024*98 = 100352 >= NN
__global__ void __launch_bounds__(SCAN_T) k_scan() {
    __shared__ int part[SCAN_T];
    int t = threadIdx.x;
    int st = t * SCAN_CHUNK;
    int s = 0;
    for (int i = 0; i < SCAN_CHUNK; i++) {
        int idx = st + i;
        if (idx < NN) s += g_deg[idx];
    }
    part[t] = s;
    __syncthreads();
    for (int off = 1; off < SCAN_T; off <<= 1) {
        int v = 0;
        if (t >= off) v = part[t - off];
        __syncthreads();
        part[t] += v;
        __syncthreads();
    }
    int run = part[t] - s;  // exclusive prefix
    for (int i = 0; i < SCAN_CHUNK; i++) {
        int idx = st + i;
        if (idx < NN) { g_rowptr[idx] = run; run += g_deg[idx]; }
    }
    if (t == SCAN_T - 1) g_rowptr[NN] = part[SCAN_T - 1];
}

__global__ void __launch_bounds__(256) k_dinv() {
    int v = blockIdx.x * 256 + threadIdx.x;
    float lg = 0.f;
    if (v < NN) {
        int d = g_deg[v];
        g_dinv[v] = rsqrtf((float)(d + 1));   // self-loop degree
        g_cursor[v] = g_rowptr[v];
        lg = log1pf((float)d);
    }
    for (int o = 16; o; o >>= 1) lg += __shfl_down_sync(0xffffffffu, lg, o);
    __shared__ float ws[8];
    int w = threadIdx.x >> 5, ln = threadIdx.x & 31;
    if (ln == 0) ws[w] = lg;
    __syncthreads();
    if (threadIdx.x == 0) {
        float tt = 0.f;
        for (int i = 0; i < 8; i++) tt += ws[i];
        atomicAdd(&g_avg, (double)tt);
    }
}

__global__ void __launch_bounds__(256) k_scatter(const int* __restrict__ src,
                                                 const int* __restrict__ dst) {
    int e = blockIdx.x * 256 + threadIdx.x;
    if (e < NE) {
        int d = dst[e];
        int p = atomicAdd(&g_cursor[d], 1);
        g_col[p] = src[e];
    }
}

__global__ void __launch_bounds__(256) k_h0s(const float* __restrict__ x,
                                             const float* __restrict__ Wg) {
    int idx = blockIdx.x * 256 + threadIdx.x;
    if (idx < NN * FD) {
        int v = idx / FD;
        int f = idx - v * FD;
        float h0 = x[2 * v] * Wg[f] + x[2 * v + 1] * Wg[FD + f];
        g_h0s[idx] = h0 * g_dinv[v];
    }
}

__global__ void __launch_bounds__(256) k_amp() {
    int v = blockIdx.x * 256 + threadIdx.x;
    if (v < NN) {
        float avgl = (float)(g_avg / (double)NN);
        int d = g_deg[v];
        float dc = fmaxf((float)d, 1.f);
        float lg = log1pf(dc);
        g_amp[v] = lg / avgl;
        g_att[v] = avgl / lg;
    }
}

__global__ void __launch_bounds__(256) k_gcn(const float* __restrict__ bg) {
    int tid = threadIdx.x;
    int grp = tid >> 6, f = tid & 63;
    int v = blockIdx.x * 4 + grp;
    if (f >= FD) return;
    int r0 = g_rowptr[v], r1 = g_rowptr[v + 1];
    float s = 0.f;
    for (int i = r0; i < r1; i++) {
        int u = g_col[i];
        s += g_h0s[(size_t)u * FD + f];
    }
    g_h[(size_t)v * FD + f] = g_dinv[v] * (s + g_h0s[(size_t)v * FD + f]) + bg[f];
}

// ---------------- weight precombination ----------------
__global__ void __launch_bounds__(256) k_combC(const float* __restrict__ postW,
                                               const float* __restrict__ linW) {
    int idx = blockIdx.x * 256 + threadIdx.x;
    if (idx >= NL * KPAD * CST) return;
    int l = idx / (KPAD * CST);
    int r = idx - l * (KPAD * CST);
    int k = r / CST;
    int fo = r - k * CST;
    float v = 0.f;
    if (k < 650 && fo < FD) {
        const float* wq = postW + ((size_t)l * 650 + k) * FD;
        const float* wl = linW + (size_t)l * FD * FD;
        #pragma unroll 10
        for (int j = 0; j < FD; j++) v += wq[j] * wl[j * FD + fo];
    }
    g_C[idx] = v;
}

__global__ void __launch_bounds__(256) k_combB(const float* __restrict__ postb,
                                               const float* __restrict__ linW,
                                               const float* __restrict__ linb) {
    int idx = threadIdx.x;  // NL*CST = 192 threads
    if (idx >= NL * CST) return;
    int l = idx / CST;
    int fo = idx - l * CST;
    float v = 0.f;
    if (fo < FD) {
        const float* wl = linW + (size_t)l * FD * FD;
        for (int j = 0; j < FD; j++) v += postb[l * FD + j] * wl[j * FD + fo];
        v += linb[l * FD + fo];
    }
    g_bcm[idx] = v;
}

// ---------------- per-layer kernels ----------------
__global__ void __launch_bounds__(256) kA(int l, const float* __restrict__ preW,
                                          const float* __restrict__ preb) {
    __shared__ float shW[100 * FD];
    __shared__ float shH[4][FD];
    int tid = threadIdx.x;
    const float* Wp = preW + (size_t)l * 100 * FD;
    for (int i = tid; i < 100 * FD; i += 256) shW[i] = Wp[i];
    int grp = tid >> 6, f = tid & 63;
    int v = blockIdx.x * 4 + grp;
    if (f < FD) shH[grp][f] = g_h[(size_t)v * FD + f];
    __syncthreads();
    if (f < FD) {
        float b = preb[l * FD + f];
        float yv = 0.f;
        #pragma unroll 10
        for (int k = 0; k < FD; k++) {
            float hv = shH[grp][k];
            b  += hv * shW[k * FD + f];
            yv += hv * shW[(FD + k) * FD + f];
        }
        g_base[(size_t)v * FD + f] = b;
        g_y[(size_t)v * FD + f] = yv;
    }
}

__global__ void __launch_bounds__(256) kB() {
    int tid = threadIdx.x;
    int grp = tid >> 6, f = tid & 63;
    int v = blockIdx.x * 4 + grp;
    float* ep = g_ext + (size_t)v * ES;
    if (f >= FD) {
        int p = f - FD;
        if (p < ES - 650) ep[650 + p] = 0.f;   // K padding
        return;
    }
    float base = g_base[(size_t)v * FD + f];
    int r0 = g_rowptr[v], r1 = g_rowptr[v + 1];
    float s = 0.f, ss = 0.f, mn = INFINITY, mx = -INFINITY;
    for (int i = r0; i < r1; i++) {
        int u = g_col[i];
        float h = base + g_y[(size_t)u * FD + f];
        s += h; ss += h * h;
        mn = fminf(mn, h); mx = fmaxf(mx, h);
    }
    int deg = r1 - r0;
    float dc = fmaxf((float)deg, 1.f);
    float mean = s / dc;
    float msq = ss / dc;
    float var = fmaxf(msq - mean * mean, 0.f);
    float sd = sqrtf(var + 1e-5f);
    if (deg == 0) { mn = 0.f; mx = 0.f; }
    float am = g_amp[v], at = g_att[v];
    ep[f]        = g_h[(size_t)v * FD + f];
    ep[50 + f]   = mean;      ep[100 + f] = mn;      ep[150 + f] = mx;      ep[200 + f] = sd;
    ep[250 + f]  = am * mean; ep[300 + f] = am * mn; ep[350 + f] = am * mx; ep[400 + f] = am * sd;
    ep[450 + f]  = at * mean; ep[500 + f] = at * mn; ep[550 + f] = at * mx; ep[600 + f] = at * sd;
}

__global__ void __launch_bounds__(128) k_zero_bn() {
    int i = threadIdx.x;
    if (i < 2 * CST) g_bns[i] = 0.0;
}

// GEMM: O[v][fo] = ext[v][0:656] @ C[l][0:656][fo] + bc, fused BN-stat partials
__global__ void __launch_bounds__(256) kC(int l) {
    __shared__ float Ash[16][64];
    __shared__ float Bsh[16][64];
    __shared__ float redS[64];
    __shared__ float redQ[64];
    const float* __restrict__ Bp = g_C + (size_t)l * KPAD * CST;
    int tid = threadIdx.x;
    int c = tid & 31;    // fo pair index (fo = 2c, 2c+1)
    int r = tid >> 5;    // node octet 0..7
    int v0 = blockIdx.x * 64;
    float acc[16];
    #pragma unroll
    for (int i = 0; i < 16; i++) acc[i] = 0.f;
    int an = tid >> 2, kq = tid & 3;
    int av = v0 + an;
    const float4* Arow = (const float4*)(g_ext + (size_t)av * ES);
    for (int k0 = 0; k0 < KPAD; k0 += 16) {
        float4 a4 = (av < NN) ? Arow[(k0 >> 2) + kq] : make_float4(0.f, 0.f, 0.f, 0.f);
        __syncthreads();
        Ash[kq * 4 + 0][an] = a4.x;
        Ash[kq * 4 + 1][an] = a4.y;
        Ash[kq * 4 + 2][an] = a4.z;
        Ash[kq * 4 + 3][an] = a4.w;
        #pragma unroll
        for (int t = 0; t < 4; t++) {
            int i = tid + 256 * t;
            Bsh[i >> 6][i & 63] = Bp[(size_t)(k0 + (i >> 6)) * CST + (i & 63)];
        }
        __syncthreads();
        #pragma unroll
        for (int k = 0; k < 16; k++) {
            float2 b = *(const float2*)&Bsh[k][2 * c];
            float4 a0 = *(const float4*)&Ash[k][r * 8];
            float4 a1 = *(const float4*)&Ash[k][r * 8 + 4];
            acc[0]  += a0.x * b.x; acc[1]  += a0.x * b.y;
            acc[2]  += a0.y * b.x; acc[3]  += a0.y * b.y;
            acc[4]  += a0.z * b.x; acc[5]  += a0.z * b.y;
            acc[6]  += a0.w * b.x; acc[7]  += a0.w * b.y;
            acc[8]  += a1.x * b.x; acc[9]  += a1.x * b.y;
            acc[10] += a1.y * b.x; acc[11] += a1.y * b.y;
            acc[12] += a1.z * b.x; acc[13] += a1.z * b.y;
            acc[14] += a1.w * b.x; acc[15] += a1.w * b.y;
        }
    }
    int fo = 2 * c;
    bool act = (fo < FD);   // fo even <= 48 => fo+1 < FD too
    float bb0 = g_bcm[l * CST + fo], bb1 = g_bcm[l * CST + fo + 1];
    float s0 = 0.f, s1 = 0.f, q0 = 0.f, q1 = 0.f;
    #pragma unroll
    for (int n = 0; n < 8; n++) {
        int v = v0 + r * 8 + n;
        if (v < NN && act) {
            float o0 = acc[2 * n] + bb0;
            float o1 = acc[2 * n + 1] + bb1;
            *(float2*)&g_h2[(size_t)v * FD + fo] = make_float2(o0, o1);
            s0 += o0; q0 += o0 * o0;
            s1 += o1; q1 += o1 * o1;
        }
    }
    if (tid < 64) { redS[tid] = 0.f; redQ[tid] = 0.f; }
    __syncthreads();
    if (act) {
        atomicAdd(&redS[fo], s0);     atomicAdd(&redQ[fo], q0);
        atomicAdd(&redS[fo + 1], s1); atomicAdd(&redQ[fo + 1], q1);
    }
    __syncthreads();
    if (tid < 64) {
        atomicAdd(&g_bns[tid], (double)redS[tid]);
        atomicAdd(&g_bns[64 + tid], (double)redQ[tid]);
    }
}

__global__ void __launch_bounds__(64) kD(int l, const float* __restrict__ gam,
                                         const float* __restrict__ bet) {
    int f = threadIdx.x;
    if (f < FD) {
        double mu = g_bns[f] / (double)NN;
        double var = g_bns[64 + f] / (double)NN - mu * mu;
        if (var < 0.0) var = 0.0;
        double rs = 1.0 / sqrt(var + 1e-5);
        float sc = (float)rs * gam[l * FD + f];
        g_scale[f] = sc;
        g_shift[f] = bet[l * FD + f] - (float)mu * sc;
    }
}

__global__ void __launch_bounds__(256) kE() {
    int idx = blockIdx.x * 256 + threadIdx.x;
    if (idx < NN * FD) {
        int v = idx / FD;
        int f = idx - v * FD;
        float h = g_h2[idx] * g_scale[f] + g_shift[f];
        g_h[idx] = fmaxf(h, 0.f);
    }
}

// ---------------- readout ----------------
__global__ void __launch_bounds__(256) k_zero_g() {
    int i = blockIdx.x * 256 + threadIdx.x;
    if (i < NG * FD) g_gr[i] = 0.f;
}

__global__ void __launch_bounds__(64) kF(const int* __restrict__ batch) {
    int f = threadIdx.x;  // 64 lanes
    int v0 = blockIdx.x * 256;
    int vend = min(v0 + 256, NN);
    float acc = 0.f;
    int cur = batch[v0];
    for (int v = v0; v < vend; v++) {
        int b = batch[v];
        if (b != cur) {
            if (f < FD) atomicAdd(&g_gr[cur * FD + f], acc);
            acc = 0.f;
            cur = b;
        }
        if (f < FD) acc += g_h[(size_t)v * FD + f];
    }
    if (f < FD) atomicAdd(&g_gr[cur * FD + f], acc);
}

__global__ void __launch_bounds__(32) kG(const float* __restrict__ W1,
                                         const float* __restrict__ b1,
                                         const float* __restrict__ W2,
                                         const float* __restrict__ b2,
                                         float* __restrict__ out) {
    int gid = blockIdx.x, j = threadIdx.x;
    float p = 0.f;
    if (j < 25) {
        float h = b1[j];
        #pragma unroll 10
        for (int ff = 0; ff < FD; ff++) h += g_gr[gid * FD + ff] * W1[ff * 25 + j];
        h = fmaxf(h, 0.f);
        p = h * W2[j];
    }
    for (int o = 16; o; o >>= 1) p += __shfl_down_sync(0xffffffffu, p, o);
    if (j == 0) out[gid] = p + b2[0];
}

// ---------------- launch ----------------
extern "C" void kernel_launch(void* const* d_in, const int* in_sizes, int n_in,
                              void* d_out, int out_size) {
    const float* x     = (const float*)d_in[0];
    const int*   ei    = (const int*)d_in[1];
    const int*   batch = (const int*)d_in[2];
    const float* Wg    = (const float*)d_in[3];
    const float* bg    = (const float*)d_in[4];
    const float* preW  = (const float*)d_in[5];
    const float* preb  = (const float*)d_in[6];
    const float* postW = (const float*)d_in[7];
    const float* postb = (const float*)d_in[8];
    const float* linW  = (const float*)d_in[9];
    const float* linb  = (const float*)d_in[10];
    const float* gam   = (const float*)d_in[11];
    const float* bet   = (const float*)d_in[12];
    const float* W1    = (const float*)d_in[13];
    const float* b1    = (const float*)d_in[14];
    const float* W2    = (const float*)d_in[15];
    const float* b2    = (const float*)d_in[16];
    float* out = (float*)d_out;

    const int* srcp = ei;
    const int* dstp = ei + NE;

    k_zero0<<<(NN + 255) / 256, 256>>>();
    k_hist<<<(NE + 255) / 256, 256>>>(dstp);
    k_scan<<<1, SCAN_T>>>();
    k_dinv<<<(NN + 255) / 256, 256>>>();
    k_scatter<<<(NE + 255) / 256, 256>>>(srcp, dstp);
    k_h0s<<<(NN * FD + 255) / 256, 256>>>(x, Wg);
    k_amp<<<(NN + 255) / 256, 256>>>();
    k_gcn<<<NN / 4, 256>>>(bg);
    k_combC<<<(NL * KPAD * CST + 255) / 256, 256>>>(postW, linW);
    k_combB<<<1, 256>>>(postb, linW, linb);

    for (int l = 0; l < NL; l++) {
        kA<<<NN / 4, 256>>>(l, preW, preb);
        kB<<<NN / 4, 256>>>();
        k_zero_bn<<<1, 128>>>();
        kC<<<(NN + 63) / 64, 256>>>(l);
        kD<<<1, 64>>>(l, gam, bet);
        kE<<<(NN * FD + 255) / 256, 256>>>();
    }

    k_zero_g<<<(NG * FD + 255) / 256, 256>>>();
    kF<<<(NN + 255) / 256, 64>>>(batch);
    kG<<<NG, 32>>>(W1, b1, W2, b2, out);
}

// round 8
// speedup vs baseline: 1.2529x; 1.2529x over previous
#include <cuda_runtime.h>
#include <cuda_bf16.h>
#include <math.h>
#include <stdint.h>

#define NN 100000
#define NE 1600000
#define NG 64
#define FD 50
#define KPP 672       // padded K: 21 chunks of 32
#define KSTEP 32
#define NSTEP 21
#define NL 3
#define CN 64         // GEMM N (cols 50..63 zero)
#define ASTR 40       // smem row stride in bf16 units (32 + 8 pad)

// ---------------- static scratch ----------------
__device__ int    g_deg[NN];
__device__ int    g_rowptr[NN + 1];
__device__ int    g_cursor[NN];
__device__ int    g_col[NE];
__device__ float  g_dinv[NN];
__device__ float  g_amp[NN];
__device__ float  g_att[NN];
__device__ double g_avg;
__device__ float  g_h[NN * FD];
__device__ float  g_h2[NN * FD];
__device__ float  g_h0s[NN * FD];
__device__ float  g_base[NN * FD];
__device__ float  g_y[NN * FD];
__device__ __align__(16) __nv_bfloat16 g_extH[(size_t)NN * KPP];  // ~134MB
__device__ __align__(16) __nv_bfloat16 g_extL[(size_t)NN * KPP];  // ~134MB
__device__ __align__(16) __nv_bfloat16 g_CH[NL * CN * KPP];
__device__ __align__(16) __nv_bfloat16 g_CL[NL * CN * KPP];
__device__ double g_bns[2 * CN];
__device__ float  g_scale[CN];
__device__ float  g_shift[CN];
__device__ float  g_gr[NG * FD];

// ---------------- helpers ----------------
__device__ __forceinline__ uint32_t smem_u32(const void* p) {
    uint32_t a;
    asm("{ .reg .u64 t; cvta.to.shared.u64 t, %1; cvt.u32.u64 %0, t; }" : "=r"(a) : "l"(p));
    return a;
}
__device__ __forceinline__ void ldsm4(uint32_t* r, uint32_t a) {
    asm volatile("ldmatrix.sync.aligned.m8n8.x4.shared.b16 {%0,%1,%2,%3}, [%4];"
        : "=r"(r[0]), "=r"(r[1]), "=r"(r[2]), "=r"(r[3]) : "r"(a));
}
__device__ __forceinline__ void mma_bf16(float* d, const uint32_t* a, const uint32_t* b) {
    asm volatile("mma.sync.aligned.m16n8k16.row.col.f32.bf16.bf16.f32 "
        "{%0,%1,%2,%3}, {%4,%5,%6,%7}, {%8,%9}, {%0,%1,%2,%3};"
        : "+f"(d[0]), "+f"(d[1]), "+f"(d[2]), "+f"(d[3])
        : "r"(a[0]), "r"(a[1]), "r"(a[2]), "r"(a[3]), "r"(b[0]), "r"(b[1]));
}
__device__ __forceinline__ void bsplit(float v, __nv_bfloat16* H, __nv_bfloat16* L, size_t i) {
    __nv_bfloat16 h = __float2bfloat16(v);
    H[i] = h;
    L[i] = __float2bfloat16(v - __bfloat162float(h));
}

// ---------------- setup kernels ----------------
__global__ void __launch_bounds__(256) k_zero0() {
    int i = blockIdx.x * 256 + threadIdx.x;
    if (i < NN) g_deg[i] = 0;
    if (i == 0) g_avg = 0.0;
}

__global__ void __launch_bounds__(256) k_hist(const int* __restrict__ dst) {
    int e = blockIdx.x * 256 + threadIdx.x;
    if (e < NE) atomicAdd(&g_deg[dst[e]], 1);
}

#define SCAN_T 1024
#define SCAN_CHUNK 98
__global__ void __launch_bounds__(SCAN_T) k_scan() {
    __shared__ int part[SCAN_T];
    int t = threadIdx.x;
    int st = t * SCAN_CHUNK;
    int s = 0;
    for (int i = 0; i < SCAN_CHUNK; i++) {
        int idx = st + i;
        if (idx < NN) s += g_deg[idx];
    }
    part[t] = s;
    __syncthreads();
    for (int off = 1; off < SCAN_T; off <<= 1) {
        int v = 0;
        if (t >= off) v = part[t - off];
        __syncthreads();
        part[t] += v;
        __syncthreads();
    }
    int run = part[t] - s;
    for (int i = 0; i < SCAN_CHUNK; i++) {
        int idx = st + i;
        if (idx < NN) { g_rowptr[idx] = run; run += g_deg[idx]; }
    }
    if (t == SCAN_T - 1) g_rowptr[NN] = part[SCAN_T - 1];
}

__global__ void __launch_bounds__(256) k_dinv() {
    int v = blockIdx.x * 256 + threadIdx.x;
    float lg = 0.f;
    if (v < NN) {
        int d = g_deg[v];
        g_dinv[v] = rsqrtf((float)(d + 1));
        g_cursor[v] = g_rowptr[v];
        lg = log1pf((float)d);
    }
    for (int o = 16; o; o >>= 1) lg += __shfl_down_sync(0xffffffffu, lg, o);
    __shared__ float ws[8];
    int w = threadIdx.x >> 5, ln = threadIdx.x & 31;
    if (ln == 0) ws[w] = lg;
    __syncthreads();
    if (threadIdx.x == 0) {
        float tt = 0.f;
        for (int i = 0; i < 8; i++) tt += ws[i];
        atomicAdd(&g_avg, (double)tt);
    }
}

__global__ void __launch_bounds__(256) k_scatter(const int* __restrict__ src,
                                                 const int* __restrict__ dst) {
    int e = blockIdx.x * 256 + threadIdx.x;
    if (e < NE) {
        int d = dst[e];
        int p = atomicAdd(&g_cursor[d], 1);
        g_col[p] = src[e];
    }
}

__global__ void __launch_bounds__(256) k_h0s(const float* __restrict__ x,
                                             const float* __restrict__ Wg) {
    int idx = blockIdx.x * 256 + threadIdx.x;
    if (idx < NN * FD) {
        int v = idx / FD;
        int f = idx - v * FD;
        float h0 = x[2 * v] * Wg[f] + x[2 * v + 1] * Wg[FD + f];
        g_h0s[idx] = h0 * g_dinv[v];
    }
}

__global__ void __launch_bounds__(256) k_amp() {
    int v = blockIdx.x * 256 + threadIdx.x;
    if (v < NN) {
        float avgl = (float)(g_avg / (double)NN);
        int d = g_deg[v];
        float dc = fmaxf((float)d, 1.f);
        float lg = log1pf(dc);
        g_amp[v] = lg / avgl;
        g_att[v] = avgl / lg;
    }
}

__global__ void __launch_bounds__(256) k_gcn(const float* __restrict__ bg) {
    int tid = threadIdx.x;
    int grp = tid >> 6, f = tid & 63;
    int v = blockIdx.x * 4 + grp;
    if (f >= FD) return;
    int r0 = g_rowptr[v], r1 = g_rowptr[v + 1];
    float s = 0.f;
    for (int i = r0; i < r1; i++) {
        int u = g_col[i];
        s += g_h0s[(size_t)u * FD + f];
    }
    g_h[(size_t)v * FD + f] = g_dinv[v] * (s + g_h0s[(size_t)v * FD + f]) + bg[f];
}

// ---------------- combined weights -> bf16 hi/lo, layout [l][n][k] ----------------
__global__ void __launch_bounds__(256) k_combW(const float* __restrict__ postW,
                                               const float* __restrict__ linW) {
    int idx = blockIdx.x * 256 + threadIdx.x;
    if (idx >= NL * CN * KPP) return;
    int l = idx / (CN * KPP);
    int r = idx - l * (CN * KPP);
    int n = r / KPP;
    int k = r - n * KPP;
    float v = 0.f;
    if (k < 650 && n < FD) {
        const float* wq = postW + ((size_t)l * 650 + k) * FD;
        const float* wl = linW + (size_t)l * FD * FD;
        #pragma unroll 10
        for (int j = 0; j < FD; j++) v += wq[j] * wl[j * FD + n];
    }
    bsplit(v, g_CH, g_CL, idx);
}

// ---------------- per-layer kernels ----------------
__global__ void __launch_bounds__(256) kA(int l, const float* __restrict__ preW,
                                          const float* __restrict__ preb) {
    __shared__ float shW[100 * FD];
    __shared__ float shH[4][FD];
    int tid = threadIdx.x;
    const float* Wp = preW + (size_t)l * 100 * FD;
    for (int i = tid; i < 100 * FD; i += 256) shW[i] = Wp[i];
    int grp = tid >> 6, f = tid & 63;
    int v = blockIdx.x * 4 + grp;
    if (f < FD) shH[grp][f] = g_h[(size_t)v * FD + f];
    __syncthreads();
    if (f < FD) {
        float b = preb[l * FD + f];
        float yv = 0.f;
        #pragma unroll 10
        for (int k = 0; k < FD; k++) {
            float hv = shH[grp][k];
            b  += hv * shW[k * FD + f];
            yv += hv * shW[(FD + k) * FD + f];
        }
        g_base[(size_t)v * FD + f] = b;
        g_y[(size_t)v * FD + f] = yv;
    }
}

__global__ void __launch_bounds__(256) kB() {
    int tid = threadIdx.x;
    int grp = tid >> 6, f = tid & 63;
    int v = blockIdx.x * 4 + grp;
    __nv_bfloat16* eh = g_extH + (size_t)v * KPP;
    __nv_bfloat16* el = g_extL + (size_t)v * KPP;
    if (f >= FD) {
        for (int p = 650 + (f - FD); p < KPP; p += 14) {
            eh[p] = __float2bfloat16(0.f);
            el[p] = __float2bfloat16(0.f);
        }
        return;
    }
    float base = g_base[(size_t)v * FD + f];
    int r0 = g_rowptr[v], r1 = g_rowptr[v + 1];
    float s = 0.f, ss = 0.f, mn = INFINITY, mx = -INFINITY;
    for (int i = r0; i < r1; i++) {
        int u = g_col[i];
        float h = base + g_y[(size_t)u * FD + f];
        s += h; ss += h * h;
        mn = fminf(mn, h); mx = fmaxf(mx, h);
    }
    int deg = r1 - r0;
    float dc = fmaxf((float)deg, 1.f);
    float mean = s / dc;
    float msq = ss / dc;
    float var = fmaxf(msq - mean * mean, 0.f);
    float sd = sqrtf(var + 1e-5f);
    if (deg == 0) { mn = 0.f; mx = 0.f; }
    float am = g_amp[v], at = g_att[v];
    bsplit(g_h[(size_t)v * FD + f], eh, el, f);
    bsplit(mean,      eh, el, 50 + f);
    bsplit(mn,        eh, el, 100 + f);
    bsplit(mx,        eh, el, 150 + f);
    bsplit(sd,        eh, el, 200 + f);
    bsplit(am * mean, eh, el, 250 + f);
    bsplit(am * mn,   eh, el, 300 + f);
    bsplit(am * mx,   eh, el, 350 + f);
    bsplit(am * sd,   eh, el, 400 + f);
    bsplit(at * mean, eh, el, 450 + f);
    bsplit(at * mn,   eh, el, 500 + f);
    bsplit(at * mx,   eh, el, 550 + f);
    bsplit(at * sd,   eh, el, 600 + f);
}

__global__ void __launch_bounds__(128) k_zero_bn() {
    int i = threadIdx.x;
    if (i < 2 * CN) g_bns[i] = 0.0;
}

// ---------------- mma.sync GEMM: h2[v][n] = ext[v][:] @ C[l][:][n] ----------------
// Split bf16: D = Ah*Bh + Ah*Bl + Al*Bh (fp32 accumulate).
// CTA: 128 nodes x 64 cols, 8 warps each 32x32, K staged 32/iter.
__global__ void __launch_bounds__(256) kC_mma(int l) {
    __shared__ __align__(16) __nv_bfloat16 sAh[128 * ASTR];
    __shared__ __align__(16) __nv_bfloat16 sAl[128 * ASTR];
    __shared__ __align__(16) __nv_bfloat16 sBh[64 * ASTR];
    __shared__ __align__(16) __nv_bfloat16 sBl[64 * ASTR];
    int tid = threadIdx.x, lane = tid & 31, wid = tid >> 5;
    int wm = wid & 3, wn = wid >> 2;   // M offset 32*wm, N offset 32*wn
    int v0 = blockIdx.x * 128;

    float acc[2][4][4] = {};

    uint32_t bAh = smem_u32(sAh), bAl = smem_u32(sAl);
    uint32_t bBh = smem_u32(sBh), bBl = smem_u32(sBl);
    int lr = lane & 15, lh = lane >> 4;          // A ldmatrix lane split
    int bgrp = lane >> 3, bli = lane & 7;        // B ldmatrix lane split

    for (int s = 0; s < NSTEP; s++) {
        int k0 = s * KSTEP;
        __syncthreads();
        // stage A: 128 rows x 32 bf16 hi/lo (512 uint4 each; 2/thread)
        #pragma unroll
        for (int t = 0; t < 2; t++) {
            int c = tid + 256 * t;
            int r = c >> 2, q = c & 3;
            int v = v0 + r;
            uint4 h4 = make_uint4(0, 0, 0, 0), l4 = h4;
            if (v < NN) {
                const uint4* ph = (const uint4*)(g_extH + (size_t)v * KPP + k0);
                const uint4* pl = (const uint4*)(g_extL + (size_t)v * KPP + k0);
                h4 = ph[q]; l4 = pl[q];
            }
            *(uint4*)(sAh + r * ASTR + q * 8) = h4;
            *(uint4*)(sAl + r * ASTR + q * 8) = l4;
        }
        // stage B: 64 rows(n) x 32 bf16 hi/lo (256 uint4 each; 1/thread)
        {
            int n = tid >> 2, q = tid & 3;
            const uint4* ph = (const uint4*)(g_CH + ((size_t)l * CN + n) * KPP + k0);
            const uint4* pl = (const uint4*)(g_CL + ((size_t)l * CN + n) * KPP + k0);
            *(uint4*)(sBh + n * ASTR + q * 8) = ph[q];
            *(uint4*)(sBl + n * ASTR + q * 8) = pl[q];
        }
        __syncthreads();

        #pragma unroll
        for (int kk = 0; kk < 2; kk++) {
            uint32_t ah[2][4], al[2][4], bh[4][2], bl[4][2];
            #pragma unroll
            for (int im = 0; im < 2; im++) {
                uint32_t off = (uint32_t)(((wm * 32 + im * 16 + lr) * ASTR + kk * 16 + lh * 8) * 2);
                ldsm4(ah[im], bAh + off);
                ldsm4(al[im], bAl + off);
            }
            #pragma unroll
            for (int jg = 0; jg < 2; jg++) {
                uint32_t off = (uint32_t)(((wn * 32 + jg * 16 + (bgrp >> 1) * 8 + bli) * ASTR
                                           + kk * 16 + (bgrp & 1) * 8) * 2);
                uint32_t r[4];
                ldsm4(r, bBh + off);
                bh[jg * 2][0] = r[0]; bh[jg * 2][1] = r[1];
                bh[jg * 2 + 1][0] = r[2]; bh[jg * 2 + 1][1] = r[3];
                ldsm4(r, bBl + off);
                bl[jg * 2][0] = r[0]; bl[jg * 2][1] = r[1];
                bl[jg * 2 + 1][0] = r[2]; bl[jg * 2 + 1][1] = r[3];
            }
            #pragma unroll
            for (int im = 0; im < 2; im++)
                #pragma unroll
                for (int jn = 0; jn < 4; jn++) {
                    mma_bf16(acc[im][jn], ah[im], bh[jn]);
                    mma_bf16(acc[im][jn], ah[im], bl[jn]);
                    mma_bf16(acc[im][jn], al[im], bh[jn]);
                }
        }
    }

    // epilogue: D m16n8 frag layout -> g_h2 (only cols < 50)
    #pragma unroll
    for (int im = 0; im < 2; im++) {
        int r0 = v0 + wm * 32 + im * 16 + (lane >> 2);
        #pragma unroll
        for (int jn = 0; jn < 4; jn++) {
            int cb = wn * 32 + jn * 8 + (lane & 3) * 2;
            if (cb < FD) {
                if (r0 < NN)
                    *(float2*)&g_h2[(size_t)r0 * FD + cb] =
                        make_float2(acc[im][jn][0], acc[im][jn][1]);
                if (r0 + 8 < NN)
                    *(float2*)&g_h2[(size_t)(r0 + 8) * FD + cb] =
                        make_float2(acc[im][jn][2], acc[im][jn][3]);
            }
        }
    }
}

__global__ void __launch_bounds__(64) k_bnstat() {
    int f = threadIdx.x;
    if (f >= FD) return;
    int v0 = blockIdx.x * 256;
    int ve = min(v0 + 256, NN);
    float s = 0.f, q = 0.f;
    for (int v = v0; v < ve; v++) {
        float h = g_h2[(size_t)v * FD + f];
        s += h; q += h * h;
    }
    atomicAdd(&g_bns[f], (double)s);
    atomicAdd(&g_bns[CN + f], (double)q);
}

__global__ void __launch_bounds__(64) kD(int l, const float* __restrict__ gam,
                                         const float* __restrict__ bet) {
    int f = threadIdx.x;
    if (f < FD) {
        double mu = g_bns[f] / (double)NN;
        double var = g_bns[CN + f] / (double)NN - mu * mu;
        if (var < 0.0) var = 0.0;
        double rs = 1.0 / sqrt(var + 1e-5);
        float sc = (float)rs * gam[l * FD + f];
        g_scale[f] = sc;
        g_shift[f] = bet[l * FD + f] - (float)mu * sc;
    }
}

__global__ void __launch_bounds__(256) kE() {
    int idx = blockIdx.x * 256 + threadIdx.x;
    if (idx < NN * FD) {
        int v = idx / FD;
        int f = idx - v * FD;
        float h = g_h2[idx] * g_scale[f] + g_shift[f];
        g_h[idx] = fmaxf(h, 0.f);
    }
}

// ---------------- readout ----------------
__global__ void __launch_bounds__(256) k_zero_g() {
    int i = blockIdx.x * 256 + threadIdx.x;
    if (i < NG * FD) g_gr[i] = 0.f;
}

__global__ void __launch_bounds__(64) kF(const int* __restrict__ batch) {
    int f = threadIdx.x;
    int v0 = blockIdx.x * 256;
    int vend = min(v0 + 256, NN);
    float acc = 0.f;
    int cur = batch[v0];
    for (int v = v0; v < vend; v++) {
        int b = batch[v];
        if (b != cur) {
            if (f < FD) atomicAdd(&g_gr[cur * FD + f], acc);
            acc = 0.f;
            cur = b;
        }
        if (f < FD) acc += g_h[(size_t)v * FD + f];
    }
    if (f < FD) atomicAdd(&g_gr[cur * FD + f], acc);
}

__global__ void __launch_bounds__(32) kG(const float* __restrict__ W1,
                                         const float* __restrict__ b1,
                                         const float* __restrict__ W2,
                                         const float* __restrict__ b2,
                                         float* __restrict__ out) {
    int gid = blockIdx.x, j = threadIdx.x;
    float p = 0.f;
    if (j < 25) {
        float h = b1[j];
        #pragma unroll 10
        for (int ff = 0; ff < FD; ff++) h += g_gr[gid * FD + ff] * W1[ff * 25 + j];
        h = fmaxf(h, 0.f);
        p = h * W2[j];
    }
    for (int o = 16; o; o >>= 1) p += __shfl_down_sync(0xffffffffu, p, o);
    if (j == 0) out[gid] = p + b2[0];
}

// ---------------- launch ----------------
extern "C" void kernel_launch(void* const* d_in, const int* in_sizes, int n_in,
                              void* d_out, int out_size) {
    const float* x     = (const float*)d_in[0];
    const int*   ei    = (const int*)d_in[1];
    const int*   batch = (const int*)d_in[2];
    const float* Wg    = (const float*)d_in[3];
    const float* bg    = (const float*)d_in[4];
    const float* preW  = (const float*)d_in[5];
    const float* preb  = (const float*)d_in[6];
    const float* postW = (const float*)d_in[7];
    const float* linW  = (const float*)d_in[9];
    const float* gam   = (const float*)d_in[11];
    const float* bet   = (const float*)d_in[12];
    const float* W1    = (const float*)d_in[13];
    const float* b1    = (const float*)d_in[14];
    const float* W2    = (const float*)d_in[15];
    const float* b2    = (const float*)d_in[16];
    float* out = (float*)d_out;

    const int* srcp = ei;
    const int* dstp = ei + NE;

    k_zero0<<<(NN + 255) / 256, 256>>>();
    k_hist<<<(NE + 255) / 256, 256>>>(dstp);
    k_scan<<<1, SCAN_T>>>();
    k_dinv<<<(NN + 255) / 256, 256>>>();
    k_scatter<<<(NE + 255) / 256, 256>>>(srcp, dstp);
    k_h0s<<<(NN * FD + 255) / 256, 256>>>(x, Wg);
    k_amp<<<(NN + 255) / 256, 256>>>();
    k_gcn<<<NN / 4, 256>>>(bg);
    k_combW<<<(NL * CN * KPP + 255) / 256, 256>>>(postW, linW);

    for (int l = 0; l < NL; l++) {
        kA<<<NN / 4, 256>>>(l, preW, preb);
        kB<<<NN / 4, 256>>>();
        k_zero_bn<<<1, 128>>>();
        kC_mma<<<(NN + 127) / 128, 256>>>(l);
        k_bnstat<<<(NN + 255) / 256, 64>>>();
        kD<<<1, 64>>>(l, gam, bet);
        kE<<<(NN * FD + 255) / 256, 256>>>();
    }

    k_zero_g<<<(NG * FD + 255) / 256, 256>>>();
    kF<<<(NN + 255) / 256, 64>>>(batch);
    kG<<<NG, 32>>>(W1, b1, W2, b2, out);
}